// round 9
// baseline (speedup 1.0000x reference)
#include <cuda_runtime.h>
#include <cuda_bf16.h>
#include <math_constants.h>

// Problem constants
#define BATCH 4
#define T_LEN 4096
#define EMBD 32
#define HEAD 32
#define BT (BATCH * T_LEN)

// Flash tiling
#define NTHR 128        // threads per CTA
#define QPT 2           // queries per thread (adjacent rows)
#define QTILE (NTHR * QPT)   // 256 queries per CTA
#define BC 128          // key tile held in smem
#define NSPLIT 16       // key-dimension splits for occupancy / load balance
#define SPLIT_LEN (T_LEN / NSPLIT)

// scale * log2(e): scores kept in log2 domain so softmax exp is one MUFU.EX2
#define SCALE2 0.25505654309411853f   // (1/sqrt(32)) * log2(e)

typedef unsigned long long u64;

// -------- device scratch (static globals; no allocation) --------
__device__ float g_q[BT * HEAD];
__device__ float g_k[BT * HEAD];
__device__ float g_v[BT * HEAD];
__device__ float g_m[NSPLIT * BT];
__device__ float g_l[NSPLIT * BT];
__device__ float g_acc[NSPLIT * BT * HEAD];   // only read where w!=0

__device__ __forceinline__ float exp2_approx(float x) {
    float y;
    asm("ex2.approx.ftz.f32 %0, %1;" : "=f"(y) : "f"(x));
    return y;
}
// ---- packed fp32x2 ops (Blackwell FFMA2 path; ptxas won't emit these from C++) ----
__device__ __forceinline__ u64 pack2(float lo, float hi) {
    u64 r; asm("mov.b64 %0, {%1, %2};" : "=l"(r) : "f"(lo), "f"(hi)); return r;
}
__device__ __forceinline__ void unpack2(u64 v, float& lo, float& hi) {
    asm("mov.b64 {%0, %1}, %2;" : "=f"(lo), "=f"(hi) : "l"(v));
}
__device__ __forceinline__ u64 ffma2(u64 a, u64 b, u64 c) {
    u64 d; asm("fma.rn.f32x2 %0, %1, %2, %3;" : "=l"(d) : "l"(a), "l"(b), "l"(c)); return d;
}
__device__ __forceinline__ u64 fmul2(u64 a, u64 b) {
    u64 d; asm("mul.rn.f32x2 %0, %1, %2;" : "=l"(d) : "l"(a), "l"(b)); return d;
}
__device__ __forceinline__ u64 fadd2(u64 a, u64 b) {
    u64 d; asm("add.rn.f32x2 %0, %1, %2;" : "=l"(d) : "l"(a), "l"(b)); return d;
}

// ---------------- Kernel 1: QKV projection ----------------
// block = 256 threads; 32 token rows per block (4 rows per thread) so the
// shared-W fill is amortized 4x. W stored transposed [d][h], pitch 33.
#define WPITCH (HEAD + 1)
#define PROJ_ROWS 32
__global__ void proj_kernel(const float* __restrict__ x,
                            const float* __restrict__ Wq,
                            const float* __restrict__ Wk,
                            const float* __restrict__ Wv) {
    __shared__ float sWq[EMBD * WPITCH];
    __shared__ float sWk[EMBD * WPITCH];
    __shared__ float sWv[EMBD * WPITCH];
    __shared__ float sx[PROJ_ROWS][EMBD];

    int tid = threadIdx.x;
    for (int i = tid; i < EMBD * HEAD; i += 256) {
        int h = i / EMBD, d = i % EMBD;  // lanes hit stride-33 -> conflict-free
        sWq[d * WPITCH + h] = Wq[i];
        sWk[d * WPITCH + h] = Wk[i];
        sWv[d * WPITCH + h] = Wv[i];
    }
    int row0 = blockIdx.x * PROJ_ROWS;
    for (int i = tid; i < PROJ_ROWS * EMBD; i += 256) {
        int r = i >> 5, c = i & 31;
        sx[r][c] = x[(row0 + r) * EMBD + c];
    }
    __syncthreads();

    int h = tid & 31;
#pragma unroll
    for (int it = 0; it < 4; ++it) {
        int r = (tid >> 5) + 8 * it;
        float aq = 0.f, ak = 0.f, av = 0.f;
#pragma unroll
        for (int d = 0; d < EMBD; ++d) {
            float xv = sx[r][d];
            aq = fmaf(xv, sWq[d * WPITCH + h], aq);
            ak = fmaf(xv, sWk[d * WPITCH + h], ak);
            av = fmaf(xv, sWv[d * WPITCH + h], av);
        }
        int row = row0 + r;
        g_q[row * HEAD + h] = aq;
        g_k[row * HEAD + h] = ak;
        g_v[row * HEAD + h] = av;
    }
}

// ---------------- Kernel 2: flash attention partial (split-K) ----------------
// grid = (T/QTILE, NSPLIT, BATCH), block = 128 threads.
// Each thread owns TWO adjacent query rows -> every smem K/V row feeds 64 FMAs.
__global__ __launch_bounds__(NTHR) void flash_kernel() {
    __shared__ float Ks[BC * HEAD];
    __shared__ float Vs[BC * HEAD];

    int qtile = blockIdx.x, split = blockIdx.y, b = blockIdx.z;
    int tid = threadIdx.x;
    int q0 = qtile * QTILE + 2 * tid;
    int q1 = q0 + 1;

    int kv_begin = split * SPLIT_LEN;
    int kv_end = min((split + 1) * SPLIT_LEN, qtile * QTILE + QTILE);  // block-uniform
    int base0 = split * BT + (b * T_LEN + q0);
    int base1 = base0 + 1;

    if (kv_begin >= kv_end) {  // split entirely above the diagonal for all queries
        g_m[base0] = -CUDART_INF_F; g_l[base0] = 0.f;
        g_m[base1] = -CUDART_INF_F; g_l[base1] = 0.f;
        return;
    }

    const float* kb = g_k + b * T_LEN * HEAD;
    const float* vb = g_v + b * T_LEN * HEAD;

    // two q rows in packed registers
    u64 qa[16], qb[16];
    {
        const ulonglong2* qg = reinterpret_cast<const ulonglong2*>(g_q + (b * T_LEN + q0) * HEAD);
#pragma unroll
        for (int i = 0; i < 8; ++i) { ulonglong2 t = qg[i];     qa[2 * i] = t.x; qa[2 * i + 1] = t.y; }
#pragma unroll
        for (int i = 0; i < 8; ++i) { ulonglong2 t = qg[8 + i]; qb[2 * i] = t.x; qb[2 * i + 1] = t.y; }
    }

    float m0 = -CUDART_INF_F, m1 = -CUDART_INF_F;
    float l0 = 0.f, l1 = 0.f;
    u64 accA[16], accB[16];
#pragma unroll
    for (int i = 0; i < 16; ++i) { accA[i] = 0ull; accB[i] = 0ull; }

    for (int t0 = kv_begin; t0 < kv_end; t0 += BC) {
        {   // cooperative full-tile load (tile bounds always multiples of BC)
            const float4* kg = reinterpret_cast<const float4*>(kb + t0 * HEAD);
            const float4* vg = reinterpret_cast<const float4*>(vb + t0 * HEAD);
            float4* ks4 = reinterpret_cast<float4*>(Ks);
            float4* vs4 = reinterpret_cast<float4*>(Vs);
#pragma unroll
            for (int i = 0; i < 8; ++i) {
                int idx = i * NTHR + tid;
                ks4[idx] = kg[idx];
                vs4[idx] = vg[idx];
            }
        }
        __syncthreads();

        int jlim = min(BC, q1 - t0 + 1);   // may be <= 0 for threads above the diagonal
        int jcap0 = q0 - t0;               // last valid key index for q0

        for (int jj = 0; jj < jlim; jj += 4) {
            float s0[4], s1[4];
#pragma unroll
            for (int u = 0; u < 4; ++u) {
                const ulonglong2* kj = reinterpret_cast<const ulonglong2*>(Ks + (jj + u) * HEAD);
                u64 d00 = 0ull, d01 = 0ull, d02 = 0ull, d03 = 0ull;
                u64 d10 = 0ull, d11 = 0ull, d12 = 0ull, d13 = 0ull;
#pragma unroll
                for (int i = 0; i < 4; ++i) {
                    ulonglong2 ka = kj[2 * i];
                    ulonglong2 kc = kj[2 * i + 1];
                    d00 = ffma2(qa[4 * i + 0], ka.x, d00);
                    d01 = ffma2(qa[4 * i + 1], ka.y, d01);
                    d02 = ffma2(qa[4 * i + 2], kc.x, d02);
                    d03 = ffma2(qa[4 * i + 3], kc.y, d03);
                    d10 = ffma2(qb[4 * i + 0], ka.x, d10);
                    d11 = ffma2(qb[4 * i + 1], ka.y, d11);
                    d12 = ffma2(qb[4 * i + 2], kc.x, d12);
                    d13 = ffma2(qb[4 * i + 3], kc.y, d13);
                }
                u64 e0 = fadd2(fadd2(d00, d01), fadd2(d02, d03));
                u64 e1 = fadd2(fadd2(d10, d11), fadd2(d12, d13));
                float lo, hi;
                unpack2(e0, lo, hi);
                float sv0 = (lo + hi) * SCALE2;
                unpack2(e1, lo, hi);
                float sv1 = (lo + hi) * SCALE2;
                int j = jj + u;
                bool in = j < jlim;
                // faithful to reference: tril entries equal to exactly 0 are masked too
                s0[u] = (in && j <= jcap0 && sv0 != 0.0f) ? sv0 : -CUDART_INF_F;
                s1[u] = (in && sv1 != 0.0f) ? sv1 : -CUDART_INF_F;
            }

            float smax0 = fmaxf(fmaxf(s0[0], s0[1]), fmaxf(s0[2], s0[3]));
            float smax1 = fmaxf(fmaxf(s1[0], s1[1]), fmaxf(s1[2], s1[3]));
            float m0n = fmaxf(m0, smax0);
            float m1n = fmaxf(m1, smax1);
            if (m0n == -CUDART_INF_F && m1n == -CUDART_INF_F) continue;

            float c0 = 1.f, c1 = 1.f;
            float p0[4] = {0.f, 0.f, 0.f, 0.f};
            float p1[4] = {0.f, 0.f, 0.f, 0.f};
            if (m0n != -CUDART_INF_F) {
                c0 = exp2_approx(m0 - m0n);   // 0 when m0 was -inf, 1 when unchanged
                m0 = m0n;
                p0[0] = exp2_approx(s0[0] - m0n);
                p0[1] = exp2_approx(s0[1] - m0n);
                p0[2] = exp2_approx(s0[2] - m0n);
                p0[3] = exp2_approx(s0[3] - m0n);
                l0 = l0 * c0 + ((p0[0] + p0[1]) + (p0[2] + p0[3]));
            }
            if (m1n != -CUDART_INF_F) {
                c1 = exp2_approx(m1 - m1n);
                m1 = m1n;
                p1[0] = exp2_approx(s1[0] - m1n);
                p1[1] = exp2_approx(s1[1] - m1n);
                p1[2] = exp2_approx(s1[2] - m1n);
                p1[3] = exp2_approx(s1[3] - m1n);
                l1 = l1 * c1 + ((p1[0] + p1[1]) + (p1[2] + p1[3]));
            }

            u64 cc0 = pack2(c0, c0);
            u64 cc1 = pack2(c1, c1);
#pragma unroll
            for (int i = 0; i < 16; ++i) {
                accA[i] = fmul2(accA[i], cc0);
                accB[i] = fmul2(accB[i], cc1);
            }

#pragma unroll
            for (int u = 0; u < 4; ++u) {
                u64 pp0 = pack2(p0[u], p0[u]);
                u64 pp1 = pack2(p1[u], p1[u]);
                const ulonglong2* vj = reinterpret_cast<const ulonglong2*>(Vs + (jj + u) * HEAD);
#pragma unroll
                for (int i = 0; i < 8; ++i) {
                    ulonglong2 vv = vj[i];
                    accA[2 * i]     = ffma2(pp0, vv.x, accA[2 * i]);
                    accA[2 * i + 1] = ffma2(pp0, vv.y, accA[2 * i + 1]);
                    accB[2 * i]     = ffma2(pp1, vv.x, accB[2 * i]);
                    accB[2 * i + 1] = ffma2(pp1, vv.y, accB[2 * i + 1]);
                }
            }
        }
        __syncthreads();
    }

    // write partials: layout [split][b*T + q]
    g_m[base0] = m0; g_l[base0] = l0;
    g_m[base1] = m1; g_l[base1] = l1;
    ulonglong2* ag = reinterpret_cast<ulonglong2*>(g_acc + base0 * HEAD);
#pragma unroll
    for (int i = 0; i < 8; ++i) {
        ulonglong2 t; t.x = accA[2 * i]; t.y = accA[2 * i + 1];
        ag[i] = t;
    }
#pragma unroll
    for (int i = 0; i < 8; ++i) {
        ulonglong2 t; t.x = accB[2 * i]; t.y = accB[2 * i + 1];
        ag[8 + i] = t;
    }
}

// ---------------- Kernel 3: split-K combine ----------------
__global__ void combine_kernel(float* __restrict__ out) {
    int bt = blockIdx.x * blockDim.x + threadIdx.x;
    if (bt >= BT) return;

    float ms[NSPLIT], ls[NSPLIT];
    float M = -CUDART_INF_F;
#pragma unroll
    for (int s = 0; s < NSPLIT; ++s) {
        ms[s] = g_m[s * BT + bt];
        ls[s] = g_l[s * BT + bt];
        M = fmaxf(M, ms[s]);
    }
    float w[NSPLIT];
    float L = 0.f;
#pragma unroll
    for (int s = 0; s < NSPLIT; ++s) {
        w[s] = (ms[s] == -CUDART_INF_F) ? 0.f : exp2_approx(ms[s] - M);
        L = fmaf(ls[s], w[s], L);
    }
    float inv = 1.0f / L;

    float4* og = reinterpret_cast<float4*>(out + bt * HEAD);
#pragma unroll
    for (int i = 0; i < 8; ++i) {
        float4 o = make_float4(0.f, 0.f, 0.f, 0.f);
#pragma unroll
        for (int s = 0; s < NSPLIT; ++s) {
            if (w[s] != 0.f) {
                const float4 a = reinterpret_cast<const float4*>(
                    g_acc + (s * BT + bt) * HEAD)[i];
                o.x = fmaf(a.x, w[s], o.x);
                o.y = fmaf(a.y, w[s], o.y);
                o.z = fmaf(a.z, w[s], o.z);
                o.w = fmaf(a.w, w[s], o.w);
            }
        }
        o.x *= inv; o.y *= inv; o.z *= inv; o.w *= inv;
        og[i] = o;
    }
}

extern "C" void kernel_launch(void* const* d_in, const int* in_sizes, int n_in,
                              void* d_out, int out_size) {
    const float* x  = (const float*)d_in[0];
    const float* Wq = (const float*)d_in[1];
    const float* Wk = (const float*)d_in[2];
    const float* Wv = (const float*)d_in[3];
    float* out = (float*)d_out;

    proj_kernel<<<BT / PROJ_ROWS, 256>>>(x, Wq, Wk, Wv);
    flash_kernel<<<dim3(T_LEN / QTILE, NSPLIT, BATCH), NTHR>>>();
    combine_kernel<<<(BT + 127) / 128, 128>>>(out);
}

// round 12
// speedup vs baseline: 1.9522x; 1.9522x over previous
#include <cuda_runtime.h>
#include <cuda_bf16.h>
#include <math_constants.h>
#include <cstdint>

// Problem constants
#define BATCH 4
#define T_LEN 4096
#define EMBD 32
#define HEAD 32
#define BT (BATCH * T_LEN)

// Flash tiling (FA2-style, mma.sync m16n8k16 bf16)
#define NTHR 128               // 4 warps
#define QTILE 64               // queries per CTA (16 per warp)
#define BC 128                 // keys per tile
#define NSPLIT 8
#define SPLIT_LEN (T_LEN / NSPLIT)   // 512 = 4 key tiles

// scale * log2(e): scores in log2 domain -> softmax exp is one MUFU.EX2
#define SCALE2 0.25505654309411853f

typedef unsigned int u32;

// smem pitches (chosen for bank-conflict-free fragment loads)
#define KPITCH_W 18            // K row pitch in u32 words (36 bf16)
#define VTPITCH 136            // Vt row pitch in bf16 elements (68 words)

// -------- device scratch (static globals; no allocation) --------
__device__ float g_q[BT * HEAD];
__device__ float g_k[BT * HEAD];
__device__ float g_v[BT * HEAD];
__device__ float g_m[NSPLIT * BT];
__device__ float g_l[NSPLIT * BT];
__device__ float g_acc[NSPLIT * BT * HEAD];

__device__ __forceinline__ float exp2_approx(float x) {
    float y;
    asm("ex2.approx.ftz.f32 %0, %1;" : "=f"(y) : "f"(x));
    return y;
}
__device__ __forceinline__ u32 bf16pack(float a, float b) {
    __nv_bfloat16 ha = __float2bfloat16(a), hb = __float2bfloat16(b);
    return ((u32)__bfloat16_as_ushort(hb) << 16) | (u32)__bfloat16_as_ushort(ha);
}
__device__ __forceinline__ float bf16hi_f(float a) {
    return __bfloat162float(__float2bfloat16(a));
}
// m16n8k16 row.col bf16 -> f32 accumulate (baseline PTX, works on sm_103 non-'a')
__device__ __forceinline__ void mma16816(float c[4], u32 a0, u32 a1, u32 a2, u32 a3,
                                         u32 b0, u32 b1) {
    asm volatile(
        "mma.sync.aligned.m16n8k16.row.col.f32.bf16.bf16.f32 "
        "{%0,%1,%2,%3}, {%4,%5,%6,%7}, {%8,%9}, {%0,%1,%2,%3};"
        : "+f"(c[0]), "+f"(c[1]), "+f"(c[2]), "+f"(c[3])
        : "r"(a0), "r"(a1), "r"(a2), "r"(a3), "r"(b0), "r"(b1));
}

// ---------------- Kernel 1: QKV projection ----------------
#define WPITCH (HEAD + 1)
#define PROJ_ROWS 32
__global__ void proj_kernel(const float* __restrict__ x,
                            const float* __restrict__ Wq,
                            const float* __restrict__ Wk,
                            const float* __restrict__ Wv) {
    __shared__ float sWq[EMBD * WPITCH];
    __shared__ float sWk[EMBD * WPITCH];
    __shared__ float sWv[EMBD * WPITCH];
    __shared__ float sx[PROJ_ROWS][EMBD];

    int tid = threadIdx.x;
    for (int i = tid; i < EMBD * HEAD; i += 256) {
        int h = i / EMBD, d = i % EMBD;
        sWq[d * WPITCH + h] = Wq[i];
        sWk[d * WPITCH + h] = Wk[i];
        sWv[d * WPITCH + h] = Wv[i];
    }
    int row0 = blockIdx.x * PROJ_ROWS;
    for (int i = tid; i < PROJ_ROWS * EMBD; i += 256) {
        int r = i >> 5, c = i & 31;
        sx[r][c] = x[(row0 + r) * EMBD + c];
    }
    __syncthreads();

    int h = tid & 31;
#pragma unroll
    for (int it = 0; it < 4; ++it) {
        int r = (tid >> 5) + 8 * it;
        float aq = 0.f, ak = 0.f, av = 0.f;
#pragma unroll
        for (int d = 0; d < EMBD; ++d) {
            float xv = sx[r][d];
            aq = fmaf(xv, sWq[d * WPITCH + h], aq);
            ak = fmaf(xv, sWk[d * WPITCH + h], ak);
            av = fmaf(xv, sWv[d * WPITCH + h], av);
        }
        int row = row0 + r;
        g_q[row * HEAD + h] = aq;
        g_k[row * HEAD + h] = ak;
        g_v[row * HEAD + h] = av;
    }
}

// ---------------- Kernel 2: HMMA flash attention (split-K) ----------------
// grid = (T/QTILE, NSPLIT, BATCH), block = 128 (4 warps x 16 query rows each).
__global__ __launch_bounds__(NTHR) void flash_mma_kernel() {
    // K tile: [128 keys][32 h] bf16 hi/lo, row pitch 18 u32 (conflict-spread)
    __shared__ __align__(16) u32 sKh[BC * KPITCH_W];
    __shared__ __align__(16) u32 sKl[BC * KPITCH_W];
    // V tile transposed: [32 h][128 keys] bf16 hi/lo, pitch 136 bf16
    __shared__ __align__(16) __nv_bfloat16 sVh[HEAD * VTPITCH];
    __shared__ __align__(16) __nv_bfloat16 sVl[HEAD * VTPITCH];

    int qtile = blockIdx.x, split = blockIdx.y, b = blockIdx.z;
    int tid = threadIdx.x;
    int wid = tid >> 5, lane = tid & 31;
    int g = lane >> 2, t = lane & 3;

    int qbase = qtile * QTILE;
    int kv_begin = split * SPLIT_LEN;
    int kv_end = min(kv_begin + SPLIT_LEN, qbase + QTILE);   // block-uniform

    int q0 = qbase + wid * 16 + g;      // this thread's two query rows
    int q1 = q0 + 8;
    int pb0 = split * BT + b * T_LEN + q0;
    int pb1 = pb0 + 8;

    if (kv_begin >= kv_end) {           // split entirely above diagonal
        if (t == 0) {
            g_m[pb0] = -CUDART_INF_F; g_l[pb0] = 0.f;
            g_m[pb1] = -CUDART_INF_F; g_l[pb1] = 0.f;
        }
        return;
    }

    const float* kb = g_k + b * T_LEN * HEAD;
    const float* vb = g_v + b * T_LEN * HEAD;

    // ---- Q fragments (hi/lo, 2 k-steps x 4 regs), loaded once from gmem ----
    u32 qh[2][4], ql[2][4];
    {
        const float* qr0 = g_q + (b * T_LEN + q0) * HEAD;
        const float* qr1 = g_q + (b * T_LEN + q1) * HEAD;
#pragma unroll
        for (int ks = 0; ks < 2; ++ks) {
            int h0 = 16 * ks + 2 * t;
            float2 v00 = *(const float2*)(qr0 + h0);        // row g,   k=2t,2t+1
            float2 v10 = *(const float2*)(qr1 + h0);        // row g+8
            float2 v01 = *(const float2*)(qr0 + h0 + 8);    // row g,   k=2t+8,2t+9
            float2 v11 = *(const float2*)(qr1 + h0 + 8);
            qh[ks][0] = bf16pack(v00.x, v00.y);
            qh[ks][1] = bf16pack(v10.x, v10.y);
            qh[ks][2] = bf16pack(v01.x, v01.y);
            qh[ks][3] = bf16pack(v11.x, v11.y);
            ql[ks][0] = bf16pack(v00.x - bf16hi_f(v00.x), v00.y - bf16hi_f(v00.y));
            ql[ks][1] = bf16pack(v10.x - bf16hi_f(v10.x), v10.y - bf16hi_f(v10.y));
            ql[ks][2] = bf16pack(v01.x - bf16hi_f(v01.x), v01.y - bf16hi_f(v01.y));
            ql[ks][3] = bf16pack(v11.x - bf16hi_f(v11.x), v11.y - bf16hi_f(v11.y));
        }
    }

    float m0 = -CUDART_INF_F, m1 = -CUDART_INF_F;
    float l0 = 0.f, l1 = 0.f;
    float O[4][4];                      // 4 n-blocks of m16n8 accum (O is 16x32)
#pragma unroll
    for (int nb = 0; nb < 4; ++nb)
#pragma unroll
        for (int i = 0; i < 4; ++i) O[nb][i] = 0.f;

    for (int t0 = kv_begin; t0 < kv_end; t0 += BC) {
        // ---- stage K (hi/lo) and V transposed (hi/lo) ----
        __syncthreads();
        {
            const float4* kg = reinterpret_cast<const float4*>(kb + t0 * HEAD);
            const float4* vg = reinterpret_cast<const float4*>(vb + t0 * HEAD);
#pragma unroll
            for (int it = 0; it < 8; ++it) {
                int f = it * NTHR + tid;          // 1024 float4s
                int key = f >> 3, h4 = f & 7;
                float4 kv = kg[f];
                int w0 = key * KPITCH_W + h4 * 2;
                sKh[w0]     = bf16pack(kv.x, kv.y);
                sKh[w0 + 1] = bf16pack(kv.z, kv.w);
                sKl[w0]     = bf16pack(kv.x - bf16hi_f(kv.x), kv.y - bf16hi_f(kv.y));
                sKl[w0 + 1] = bf16pack(kv.z - bf16hi_f(kv.z), kv.w - bf16hi_f(kv.w));
                float4 vv = vg[f];
                float vf[4] = {vv.x, vv.y, vv.z, vv.w};
#pragma unroll
                for (int i = 0; i < 4; ++i) {
                    int h = h4 * 4 + i;
                    sVh[h * VTPITCH + key] = __float2bfloat16(vf[i]);
                    sVl[h * VTPITCH + key] = __float2bfloat16(vf[i] - bf16hi_f(vf[i]));
                }
            }
        }
        __syncthreads();

        // ---- S = Q K^T : 16 n-blocks of m16n8, 3 split-terms x 2 k-steps ----
        float sA[32], sB[32];           // row g: (c0,c1) per block; row g+8: (c2,c3)
#pragma unroll
        for (int nb = 0; nb < 16; ++nb) {
            int key = nb * 8 + g;
            const u32* krh = sKh + key * KPITCH_W;
            const u32* krl = sKl + key * KPITCH_W;
            u32 kh0 = krh[t],     kh1 = krh[t + 4];     // k-step 0
            u32 kh2 = krh[t + 8], kh3 = krh[t + 12];    // k-step 1
            u32 kl0 = krl[t],     kl1 = krl[t + 4];
            u32 kl2 = krl[t + 8], kl3 = krl[t + 12];
            float c[4] = {0.f, 0.f, 0.f, 0.f};
            mma16816(c, qh[0][0], qh[0][1], qh[0][2], qh[0][3], kh0, kh1);
            mma16816(c, qh[1][0], qh[1][1], qh[1][2], qh[1][3], kh2, kh3);
            mma16816(c, qh[0][0], qh[0][1], qh[0][2], qh[0][3], kl0, kl1);
            mma16816(c, qh[1][0], qh[1][1], qh[1][2], qh[1][3], kl2, kl3);
            mma16816(c, ql[0][0], ql[0][1], ql[0][2], ql[0][3], kh0, kh1);
            mma16816(c, ql[1][0], ql[1][1], ql[1][2], ql[1][3], kh2, kh3);
            sA[2 * nb]     = c[0]; sA[2 * nb + 1] = c[1];
            sB[2 * nb]     = c[2]; sB[2 * nb + 1] = c[3];
        }

        // ---- mask + scale + row max ----
        float mx0 = -CUDART_INF_F, mx1 = -CUDART_INF_F;
#pragma unroll
        for (int nb = 0; nb < 16; ++nb) {
#pragma unroll
            for (int i = 0; i < 2; ++i) {
                int j = t0 + nb * 8 + 2 * t + i;
                float a = sA[2 * nb + i] * SCALE2;
                float bs = sB[2 * nb + i] * SCALE2;
                // faithful: tril entries equal to exactly 0 are masked too
                a  = (j <= q0 && a  != 0.0f) ? a  : -CUDART_INF_F;
                bs = (j <= q1 && bs != 0.0f) ? bs : -CUDART_INF_F;
                sA[2 * nb + i] = a;
                sB[2 * nb + i] = bs;
                mx0 = fmaxf(mx0, a);
                mx1 = fmaxf(mx1, bs);
            }
        }
        mx0 = fmaxf(mx0, __shfl_xor_sync(0xffffffffu, mx0, 1));
        mx0 = fmaxf(mx0, __shfl_xor_sync(0xffffffffu, mx0, 2));
        mx1 = fmaxf(mx1, __shfl_xor_sync(0xffffffffu, mx1, 1));
        mx1 = fmaxf(mx1, __shfl_xor_sync(0xffffffffu, mx1, 2));
        float m0n = fmaxf(m0, mx0);
        float m1n = fmaxf(m1, mx1);
        // every tile has >= 1 unmasked col per row (t0 <= qbase <= q), so m*n finite
        float c0 = exp2_approx(m0 - m0n);   // 0 on first tile, 1 if unchanged
        float c1 = exp2_approx(m1 - m1n);
        m0 = m0n; m1 = m1n;

        // ---- exp + row sums (overwrite s with p) ----
        float ls0 = 0.f, ls1 = 0.f;
#pragma unroll
        for (int k = 0; k < 32; ++k) {
            float p0 = exp2_approx(sA[k] - m0n);   // ex2(-inf)=0 for masked
            float p1 = exp2_approx(sB[k] - m1n);
            sA[k] = p0; sB[k] = p1;
            ls0 += p0; ls1 += p1;
        }
        ls0 += __shfl_xor_sync(0xffffffffu, ls0, 1);
        ls0 += __shfl_xor_sync(0xffffffffu, ls0, 2);
        ls1 += __shfl_xor_sync(0xffffffffu, ls1, 1);
        ls1 += __shfl_xor_sync(0xffffffffu, ls1, 2);
        l0 = l0 * c0 + ls0;
        l1 = l1 * c1 + ls1;

        // ---- rescale O ----
#pragma unroll
        for (int nb = 0; nb < 4; ++nb) {
            O[nb][0] *= c0; O[nb][1] *= c0;
            O[nb][2] *= c1; O[nb][3] *= c1;
        }

        // ---- O += P V : A = P fragments (hi/lo) from s regs, B = Vt from smem ----
#pragma unroll
        for (int ks = 0; ks < 8; ++ks) {
            float pa0 = sA[4 * ks],     pa1 = sA[4 * ks + 1];
            float pb0v = sB[4 * ks],    pb1v = sB[4 * ks + 1];
            float pa2 = sA[4 * ks + 2], pa3 = sA[4 * ks + 3];
            float pb2 = sB[4 * ks + 2], pb3 = sB[4 * ks + 3];
            u32 aph0 = bf16pack(pa0, pa1);
            u32 aph1 = bf16pack(pb0v, pb1v);
            u32 aph2 = bf16pack(pa2, pa3);
            u32 aph3 = bf16pack(pb2, pb3);
            u32 apl0 = bf16pack(pa0 - bf16hi_f(pa0), pa1 - bf16hi_f(pa1));
            u32 apl1 = bf16pack(pb0v - bf16hi_f(pb0v), pb1v - bf16hi_f(pb1v));
            u32 apl2 = bf16pack(pa2 - bf16hi_f(pa2), pa3 - bf16hi_f(pa3));
            u32 apl3 = bf16pack(pb2 - bf16hi_f(pb2), pb3 - bf16hi_f(pb3));
#pragma unroll
            for (int nb = 0; nb < 4; ++nb) {
                int h = nb * 8 + g;
                const u32* vrh = reinterpret_cast<const u32*>(sVh + h * VTPITCH);
                const u32* vrl = reinterpret_cast<const u32*>(sVl + h * VTPITCH);
                u32 vh0 = vrh[8 * ks + t], vh1 = vrh[8 * ks + 4 + t];
                u32 vl0 = vrl[8 * ks + t], vl1 = vrl[8 * ks + 4 + t];
                mma16816(O[nb], aph0, aph1, aph2, aph3, vh0, vh1);
                mma16816(O[nb], aph0, aph1, aph2, aph3, vl0, vl1);
                mma16816(O[nb], apl0, apl1, apl2, apl3, vh0, vh1);
            }
        }
    }

    // ---- write partials ----
    if (t == 0) {
        g_m[pb0] = m0; g_l[pb0] = l0;
        g_m[pb1] = m1; g_l[pb1] = l1;
    }
    float* a0p = g_acc + pb0 * HEAD;
    float* a1p = g_acc + pb1 * HEAD;
#pragma unroll
    for (int nb = 0; nb < 4; ++nb) {
        int hc = nb * 8 + 2 * t;
        *(float2*)(a0p + hc) = make_float2(O[nb][0], O[nb][1]);
        *(float2*)(a1p + hc) = make_float2(O[nb][2], O[nb][3]);
    }
}

// ---------------- Kernel 3: split-K combine ----------------
__global__ void combine_kernel(float* __restrict__ out) {
    int bt = blockIdx.x * blockDim.x + threadIdx.x;
    if (bt >= BT) return;

    float ms[NSPLIT], ls[NSPLIT];
    float M = -CUDART_INF_F;
#pragma unroll
    for (int s = 0; s < NSPLIT; ++s) {
        ms[s] = g_m[s * BT + bt];
        ls[s] = g_l[s * BT + bt];
        M = fmaxf(M, ms[s]);
    }
    float w[NSPLIT];
    float L = 0.f;
#pragma unroll
    for (int s = 0; s < NSPLIT; ++s) {
        w[s] = (ms[s] == -CUDART_INF_F) ? 0.f : exp2_approx(ms[s] - M);
        L = fmaf(ls[s], w[s], L);
    }
    float inv = 1.0f / L;

    float4* og = reinterpret_cast<float4*>(out + bt * HEAD);
#pragma unroll
    for (int i = 0; i < 8; ++i) {
        float4 o = make_float4(0.f, 0.f, 0.f, 0.f);
#pragma unroll
        for (int s = 0; s < NSPLIT; ++s) {
            if (w[s] != 0.f) {
                const float4 a = reinterpret_cast<const float4*>(
                    g_acc + (s * BT + bt) * HEAD)[i];
                o.x = fmaf(a.x, w[s], o.x);
                o.y = fmaf(a.y, w[s], o.y);
                o.z = fmaf(a.z, w[s], o.z);
                o.w = fmaf(a.w, w[s], o.w);
            }
        }
        o.x *= inv; o.y *= inv; o.z *= inv; o.w *= inv;
        og[i] = o;
    }
}

extern "C" void kernel_launch(void* const* d_in, const int* in_sizes, int n_in,
                              void* d_out, int out_size) {
    const float* x  = (const float*)d_in[0];
    const float* Wq = (const float*)d_in[1];
    const float* Wk = (const float*)d_in[2];
    const float* Wv = (const float*)d_in[3];
    float* out = (float*)d_out;

    proj_kernel<<<BT / PROJ_ROWS, 256>>>(x, Wq, Wk, Wv);
    flash_mma_kernel<<<dim3(T_LEN / QTILE, NSPLIT, BATCH), NTHR>>>();
    combine_kernel<<<(BT + 127) / 128, 128>>>(out);
}

// round 13
// speedup vs baseline: 2.4175x; 1.2384x over previous
#include <cuda_runtime.h>
#include <cuda_bf16.h>
#include <math_constants.h>
#include <cstdint>

// Problem constants
#define BATCH 4
#define T_LEN 4096
#define EMBD 32
#define HEAD 32
#define BT (BATCH * T_LEN)

// Flash tiling (FA2-style, mma.sync m16n8k16 bf16)
#define NTHR 128               // 4 warps
#define QTILE 64               // queries per CTA (16 per warp)
#define BC 128                 // keys per tile
#define NSPLIT 8
#define SPLIT_LEN (T_LEN / NSPLIT)   // 512 = 4 key tiles

// scale * log2(e): scores in log2 domain -> softmax exp is one MUFU.EX2
#define SCALE2 0.25505654309411853f

typedef unsigned int u32;

// smem pitches (16B-aligned AND conflict-free for fragment reads)
#define KPITCH_W 20            // K row pitch in u32 words (80B: 16|80, banks 20g+t distinct)
#define VTPITCH_W 68           // Vt row pitch in u32 words (272B: 16|272, banks 4h+t distinct)

// -------- device scratch (static globals; no allocation) --------
// packed bf16-split operands, produced once by proj:
__device__ u32 g_qh[BT * 16];                      // [row][h2] hi
__device__ u32 g_ql[BT * 16];                      // [row][h2] lo
__device__ u32 g_kh[BT * 16];
__device__ u32 g_kl[BT * 16];
__device__ u32 g_vth[BATCH * HEAD * (T_LEN / 2)];  // [b][h][keypair] hi
__device__ u32 g_vtl[BATCH * HEAD * (T_LEN / 2)];
__device__ float g_m[NSPLIT * BT];
__device__ float g_l[NSPLIT * BT];
__device__ float g_acc[NSPLIT * BT * HEAD];

__device__ __forceinline__ float exp2_approx(float x) {
    float y;
    asm("ex2.approx.ftz.f32 %0, %1;" : "=f"(y) : "f"(x));
    return y;
}
// ---- truncation-based bf16 split packing ----
// hi = top 16 bits of fp32 (exact truncation); lo = x - hi, rn-converted.
// Residual after 3-term MMA: ~2^-16 relative (fp32-grade for this problem).
__device__ __forceinline__ u32 pack_hi2(float a, float b) {
    return __byte_perm(__float_as_uint(a), __float_as_uint(b), 0x7632);
}
__device__ __forceinline__ float trunc_hi(float a) {
    return __uint_as_float(__float_as_uint(a) & 0xFFFF0000u);
}
__device__ __forceinline__ u32 pack_lo2(float a, float b) {
    float la = a - trunc_hi(a), lb = b - trunc_hi(b);
    u32 r;
    asm("cvt.rn.bf16x2.f32 %0, %1, %2;" : "=r"(r) : "f"(lb), "f"(la));  // lo half = la
    return r;
}
// m16n8k16 row.col bf16 -> f32 accumulate (baseline PTX, works on sm_103 non-'a')
__device__ __forceinline__ void mma16816(float c[4], u32 a0, u32 a1, u32 a2, u32 a3,
                                         u32 b0, u32 b1) {
    asm volatile(
        "mma.sync.aligned.m16n8k16.row.col.f32.bf16.bf16.f32 "
        "{%0,%1,%2,%3}, {%4,%5,%6,%7}, {%8,%9}, {%0,%1,%2,%3};"
        : "+f"(c[0]), "+f"(c[1]), "+f"(c[2]), "+f"(c[3])
        : "r"(a0), "r"(a1), "r"(a2), "r"(a3), "r"(b0), "r"(b1));
}

// ---------------- Kernel 1: QKV projection + split/pack/transpose ----------------
// block = 256 threads, 32 token rows per block. Emits packed bf16-split Q/K
// ([row][16 words] hi/lo) and transposed V ([b][h][T/2 words] hi/lo).
#define WPITCH (HEAD + 1)
#define PROJ_ROWS 32
__global__ void proj_kernel(const float* __restrict__ x,
                            const float* __restrict__ Wq,
                            const float* __restrict__ Wk,
                            const float* __restrict__ Wv) {
    __shared__ float sWq[EMBD * WPITCH];
    __shared__ float sWk[EMBD * WPITCH];
    __shared__ float sWv[EMBD * WPITCH];
    __shared__ float sx[PROJ_ROWS][EMBD];
    __shared__ float sq[PROJ_ROWS][33];
    __shared__ float sk[PROJ_ROWS][33];
    __shared__ float sv[PROJ_ROWS][33];

    int tid = threadIdx.x;
    for (int i = tid; i < EMBD * HEAD; i += 256) {
        int h = i / EMBD, d = i % EMBD;
        sWq[d * WPITCH + h] = Wq[i];
        sWk[d * WPITCH + h] = Wk[i];
        sWv[d * WPITCH + h] = Wv[i];
    }
    int row0 = blockIdx.x * PROJ_ROWS;
    for (int i = tid; i < PROJ_ROWS * EMBD; i += 256) {
        int r = i >> 5, c = i & 31;
        sx[r][c] = x[(row0 + r) * EMBD + c];
    }
    __syncthreads();

    int h = tid & 31;
#pragma unroll
    for (int it = 0; it < 4; ++it) {
        int r = (tid >> 5) + 8 * it;
        float aq = 0.f, ak = 0.f, av = 0.f;
#pragma unroll
        for (int d = 0; d < EMBD; ++d) {
            float xv = sx[r][d];
            aq = fmaf(xv, sWq[d * WPITCH + h], aq);
            ak = fmaf(xv, sWk[d * WPITCH + h], ak);
            av = fmaf(xv, sWv[d * WPITCH + h], av);
        }
        sq[r][h] = aq;
        sk[r][h] = ak;
        sv[r][h] = av;
    }
    __syncthreads();

    // --- pack Q,K: word (row, h2) = bf16x2 of h = 2h2, 2h2+1 ---
    for (int i = tid; i < PROJ_ROWS * 16; i += 256) {
        int r = i >> 4, h2 = i & 15;
        float a = sq[r][2 * h2], bq = sq[r][2 * h2 + 1];
        int gi = (row0 + r) * 16 + h2;
        g_qh[gi] = pack_hi2(a, bq);
        g_ql[gi] = pack_lo2(a, bq);
        float c = sk[r][2 * h2], dk = sk[r][2 * h2 + 1];
        g_kh[gi] = pack_hi2(c, dk);
        g_kl[gi] = pack_lo2(c, dk);
    }
    // --- pack V transposed: word (h, kp) = bf16x2 of keys 2kp, 2kp+1 at dim h ---
    int bb = row0 / T_LEN;
    int trow = row0 - bb * T_LEN;
    for (int i = tid; i < HEAD * 16; i += 256) {
        int hh = i >> 4, kp = i & 15;
        float v0 = sv[2 * kp][hh], v1 = sv[2 * kp + 1][hh];
        int gi = (bb * HEAD + hh) * (T_LEN / 2) + trow / 2 + kp;
        g_vth[gi] = pack_hi2(v0, v1);
        g_vtl[gi] = pack_lo2(v0, v1);
    }
}

// ---------------- Kernel 2: HMMA flash attention (split-K) ----------------
// grid = (T/QTILE, NSPLIT, BATCH), block = 128 (4 warps x 16 query rows each).
// Staging is now pure float4 copies of pre-packed data.
__global__ __launch_bounds__(NTHR) void flash_mma_kernel() {
    __shared__ __align__(16) u32 sKh[BC * KPITCH_W];
    __shared__ __align__(16) u32 sKl[BC * KPITCH_W];
    __shared__ __align__(16) u32 sVh[HEAD * VTPITCH_W];
    __shared__ __align__(16) u32 sVl[HEAD * VTPITCH_W];

    int qtile = blockIdx.x, split = blockIdx.y, b = blockIdx.z;
    int tid = threadIdx.x;
    int wid = tid >> 5, lane = tid & 31;
    int g = lane >> 2, t = lane & 3;

    int qbase = qtile * QTILE;
    int kv_begin = split * SPLIT_LEN;
    int kv_end = min(kv_begin + SPLIT_LEN, qbase + QTILE);   // block-uniform

    int q0 = qbase + wid * 16 + g;      // this thread's two query rows
    int q1 = q0 + 8;
    int pb0 = split * BT + b * T_LEN + q0;
    int pb1 = pb0 + 8;

    if (kv_begin >= kv_end) {           // split entirely above diagonal
        if (t == 0) {
            g_m[pb0] = -CUDART_INF_F; g_l[pb0] = 0.f;
            g_m[pb1] = -CUDART_INF_F; g_l[pb1] = 0.f;
        }
        return;
    }

    // ---- Q fragments: direct u32 loads of pre-packed words ----
    u32 qh[2][4], ql[2][4];
    {
        int r0 = (b * T_LEN + q0) * 16;
        int r1 = (b * T_LEN + q1) * 16;
#pragma unroll
        for (int ks = 0; ks < 2; ++ks) {
            int w = 8 * ks + t;
            qh[ks][0] = g_qh[r0 + w];     qh[ks][1] = g_qh[r1 + w];
            qh[ks][2] = g_qh[r0 + w + 4]; qh[ks][3] = g_qh[r1 + w + 4];
            ql[ks][0] = g_ql[r0 + w];     ql[ks][1] = g_ql[r1 + w];
            ql[ks][2] = g_ql[r0 + w + 4]; ql[ks][3] = g_ql[r1 + w + 4];
        }
    }

    float m0 = -CUDART_INF_F, m1 = -CUDART_INF_F;
    float l0 = 0.f, l1 = 0.f;
    float O[4][4];
#pragma unroll
    for (int nb = 0; nb < 4; ++nb)
#pragma unroll
        for (int i = 0; i < 4; ++i) O[nb][i] = 0.f;

    for (int t0 = kv_begin; t0 < kv_end; t0 += BC) {
        // ---- stage pre-packed K (pitch 20) and Vt (pitch 68): float4 copies ----
        __syncthreads();
        {
            const float4* skh = (const float4*)(g_kh + (b * T_LEN + t0) * 16);
            const float4* skl = (const float4*)(g_kl + (b * T_LEN + t0) * 16);
#pragma unroll
            for (int it = 0; it < 4; ++it) {          // 512 float4s each
                int f = it * NTHR + tid;
                int row = f >> 2, w4 = f & 3;
                *(float4*)&sKh[row * KPITCH_W + 4 * w4] = skh[f];
                *(float4*)&sKl[row * KPITCH_W + 4 * w4] = skl[f];
            }
            const float4* svh = (const float4*)(g_vth + b * HEAD * (T_LEN / 2));
            const float4* svl = (const float4*)(g_vtl + b * HEAD * (T_LEN / 2));
            int wbase = t0 >> 3;                       // float4 offset of t0/2 words
#pragma unroll
            for (int it = 0; it < 4; ++it) {          // 512 float4s each
                int f = it * NTHR + tid;
                int hh = f >> 4, w4 = f & 15;
                int src = hh * (T_LEN / 8) + wbase + w4;
                *(float4*)&sVh[hh * VTPITCH_W + 4 * w4] = svh[src];
                *(float4*)&sVl[hh * VTPITCH_W + 4 * w4] = svl[src];
            }
        }
        __syncthreads();

        // ---- S = Q K^T : 16 n-blocks of m16n8, 3 split-terms x 2 k-steps ----
        float sA[32], sB[32];
#pragma unroll
        for (int nb = 0; nb < 16; ++nb) {
            int key = nb * 8 + g;
            const u32* krh = sKh + key * KPITCH_W;
            const u32* krl = sKl + key * KPITCH_W;
            u32 kh0 = krh[t],     kh1 = krh[t + 4];
            u32 kh2 = krh[t + 8], kh3 = krh[t + 12];
            u32 kl0 = krl[t],     kl1 = krl[t + 4];
            u32 kl2 = krl[t + 8], kl3 = krl[t + 12];
            float c[4] = {0.f, 0.f, 0.f, 0.f};
            mma16816(c, qh[0][0], qh[0][1], qh[0][2], qh[0][3], kh0, kh1);
            mma16816(c, qh[1][0], qh[1][1], qh[1][2], qh[1][3], kh2, kh3);
            mma16816(c, qh[0][0], qh[0][1], qh[0][2], qh[0][3], kl0, kl1);
            mma16816(c, qh[1][0], qh[1][1], qh[1][2], qh[1][3], kl2, kl3);
            mma16816(c, ql[0][0], ql[0][1], ql[0][2], ql[0][3], kh0, kh1);
            mma16816(c, ql[1][0], ql[1][1], ql[1][2], ql[1][3], kh2, kh3);
            sA[2 * nb]     = c[0]; sA[2 * nb + 1] = c[1];
            sB[2 * nb]     = c[2]; sB[2 * nb + 1] = c[3];
        }

        // ---- mask + scale + row max ----
        float mx0 = -CUDART_INF_F, mx1 = -CUDART_INF_F;
#pragma unroll
        for (int nb = 0; nb < 16; ++nb) {
#pragma unroll
            for (int i = 0; i < 2; ++i) {
                int j = t0 + nb * 8 + 2 * t + i;
                float a = sA[2 * nb + i] * SCALE2;
                float bs = sB[2 * nb + i] * SCALE2;
                // faithful: tril entries equal to exactly 0 are masked too
                a  = (j <= q0 && a  != 0.0f) ? a  : -CUDART_INF_F;
                bs = (j <= q1 && bs != 0.0f) ? bs : -CUDART_INF_F;
                sA[2 * nb + i] = a;
                sB[2 * nb + i] = bs;
                mx0 = fmaxf(mx0, a);
                mx1 = fmaxf(mx1, bs);
            }
        }
        mx0 = fmaxf(mx0, __shfl_xor_sync(0xffffffffu, mx0, 1));
        mx0 = fmaxf(mx0, __shfl_xor_sync(0xffffffffu, mx0, 2));
        mx1 = fmaxf(mx1, __shfl_xor_sync(0xffffffffu, mx1, 1));
        mx1 = fmaxf(mx1, __shfl_xor_sync(0xffffffffu, mx1, 2));
        float m0n = fmaxf(m0, mx0);
        float m1n = fmaxf(m1, mx1);
        float c0 = exp2_approx(m0 - m0n);
        float c1 = exp2_approx(m1 - m1n);
        m0 = m0n; m1 = m1n;

        // ---- exp + row sums ----
        float ls0 = 0.f, ls1 = 0.f;
#pragma unroll
        for (int k = 0; k < 32; ++k) {
            float p0 = exp2_approx(sA[k] - m0n);
            float p1 = exp2_approx(sB[k] - m1n);
            sA[k] = p0; sB[k] = p1;
            ls0 += p0; ls1 += p1;
        }
        ls0 += __shfl_xor_sync(0xffffffffu, ls0, 1);
        ls0 += __shfl_xor_sync(0xffffffffu, ls0, 2);
        ls1 += __shfl_xor_sync(0xffffffffu, ls1, 1);
        ls1 += __shfl_xor_sync(0xffffffffu, ls1, 2);
        l0 = l0 * c0 + ls0;
        l1 = l1 * c1 + ls1;

#pragma unroll
        for (int nb = 0; nb < 4; ++nb) {
            O[nb][0] *= c0; O[nb][1] *= c0;
            O[nb][2] *= c1; O[nb][3] *= c1;
        }

        // ---- O += P V : truncation-split P fragments, Vt from smem ----
#pragma unroll
        for (int ks = 0; ks < 8; ++ks) {
            float pa0 = sA[4 * ks],     pa1 = sA[4 * ks + 1];
            float pb0v = sB[4 * ks],    pb1v = sB[4 * ks + 1];
            float pa2 = sA[4 * ks + 2], pa3 = sA[4 * ks + 3];
            float pb2 = sB[4 * ks + 2], pb3 = sB[4 * ks + 3];
            u32 aph0 = pack_hi2(pa0, pa1);
            u32 aph1 = pack_hi2(pb0v, pb1v);
            u32 aph2 = pack_hi2(pa2, pa3);
            u32 aph3 = pack_hi2(pb2, pb3);
            u32 apl0 = pack_lo2(pa0, pa1);
            u32 apl1 = pack_lo2(pb0v, pb1v);
            u32 apl2 = pack_lo2(pa2, pa3);
            u32 apl3 = pack_lo2(pb2, pb3);
#pragma unroll
            for (int nb = 0; nb < 4; ++nb) {
                int hh = nb * 8 + g;
                const u32* vrh = sVh + hh * VTPITCH_W;
                const u32* vrl = sVl + hh * VTPITCH_W;
                u32 vh0 = vrh[8 * ks + t], vh1 = vrh[8 * ks + 4 + t];
                u32 vl0 = vrl[8 * ks + t], vl1 = vrl[8 * ks + 4 + t];
                mma16816(O[nb], aph0, aph1, aph2, aph3, vh0, vh1);
                mma16816(O[nb], aph0, aph1, aph2, aph3, vl0, vl1);
                mma16816(O[nb], apl0, apl1, apl2, apl3, vh0, vh1);
            }
        }
    }

    // ---- write partials ----
    if (t == 0) {
        g_m[pb0] = m0; g_l[pb0] = l0;
        g_m[pb1] = m1; g_l[pb1] = l1;
    }
    float* a0p = g_acc + pb0 * HEAD;
    float* a1p = g_acc + pb1 * HEAD;
#pragma unroll
    for (int nb = 0; nb < 4; ++nb) {
        int hc = nb * 8 + 2 * t;
        *(float2*)(a0p + hc) = make_float2(O[nb][0], O[nb][1]);
        *(float2*)(a1p + hc) = make_float2(O[nb][2], O[nb][3]);
    }
}

// ---------------- Kernel 3: split-K combine ----------------
__global__ void combine_kernel(float* __restrict__ out) {
    int bt = blockIdx.x * blockDim.x + threadIdx.x;
    if (bt >= BT) return;

    float ms[NSPLIT], ls[NSPLIT];
    float M = -CUDART_INF_F;
#pragma unroll
    for (int s = 0; s < NSPLIT; ++s) {
        ms[s] = g_m[s * BT + bt];
        ls[s] = g_l[s * BT + bt];
        M = fmaxf(M, ms[s]);
    }
    float w[NSPLIT];
    float L = 0.f;
#pragma unroll
    for (int s = 0; s < NSPLIT; ++s) {
        w[s] = (ms[s] == -CUDART_INF_F) ? 0.f : exp2_approx(ms[s] - M);
        L = fmaf(ls[s], w[s], L);
    }
    float inv = 1.0f / L;

    float4* og = reinterpret_cast<float4*>(out + bt * HEAD);
#pragma unroll
    for (int i = 0; i < 8; ++i) {
        float4 o = make_float4(0.f, 0.f, 0.f, 0.f);
#pragma unroll
        for (int s = 0; s < NSPLIT; ++s) {
            if (w[s] != 0.f) {
                const float4 a = reinterpret_cast<const float4*>(
                    g_acc + (s * BT + bt) * HEAD)[i];
                o.x = fmaf(a.x, w[s], o.x);
                o.y = fmaf(a.y, w[s], o.y);
                o.z = fmaf(a.z, w[s], o.z);
                o.w = fmaf(a.w, w[s], o.w);
            }
        }
        o.x *= inv; o.y *= inv; o.z *= inv; o.w *= inv;
        og[i] = o;
    }
}

extern "C" void kernel_launch(void* const* d_in, const int* in_sizes, int n_in,
                              void* d_out, int out_size) {
    const float* x  = (const float*)d_in[0];
    const float* Wq = (const float*)d_in[1];
    const float* Wk = (const float*)d_in[2];
    const float* Wv = (const float*)d_in[3];
    float* out = (float*)d_out;

    proj_kernel<<<BT / PROJ_ROWS, 256>>>(x, Wq, Wk, Wv);
    flash_mma_kernel<<<dim3(T_LEN / QTILE, NSPLIT, BATCH), NTHR>>>();
    combine_kernel<<<(BT + 127) / 128, 128>>>(out);
}

// round 16
// speedup vs baseline: 2.5168x; 1.0411x over previous
#include <cuda_runtime.h>
#include <cuda_bf16.h>
#include <math_constants.h>
#include <cstdint>

// Problem constants
#define BATCH 4
#define T_LEN 4096
#define EMBD 32
#define HEAD 32
#define BT (BATCH * T_LEN)

// Flash tiling (FA2-style, mma.sync m16n8k16 bf16)
#define NTHR 128               // 4 warps
#define QTILE 64               // queries per CTA (16 per warp)
#define BC 128                 // keys per tile
#define NSPLIT 8
#define SPLIT_LEN (T_LEN / NSPLIT)   // 512 = 4 key tiles

// scale * log2(e): scores in log2 domain -> softmax exp is one MUFU.EX2
// Folded into Q at pack time (scale commutes through the dot product).
#define SCALE2 0.25505654309411853f

typedef unsigned int u32;

// smem pitches (conflict-free for the permuted fragment accesses)
#define KPITCH_W 16            // K row pitch in u32 words (quad layout, LDS.128)
#define VTPITCH_W 72           // Vt row pitch in u32 words (pair layout, LDS.64)

// -------- device scratch (static globals; no allocation) --------
// quad-permuted packed rows: word (row, 4t+i) = bf16x2 of dims (2(t+4i), 2(t+4i)+1)
__device__ u32 g_qh[BT * 16];
__device__ u32 g_ql[BT * 16];
__device__ u32 g_kh[BT * 16];
__device__ u32 g_kl[BT * 16];
// pair-permuted transposed V: per 64-word tile block, slot 8ks+2t+i = keypair (8ks+t+4i)
__device__ u32 g_vth[BATCH * HEAD * (T_LEN / 2)];
__device__ u32 g_vtl[BATCH * HEAD * (T_LEN / 2)];
__device__ float g_m[NSPLIT * BT];
__device__ float g_l[NSPLIT * BT];
__device__ float g_acc[NSPLIT * BT * HEAD];

__device__ __forceinline__ float exp2_approx(float x) {
    float y;
    asm("ex2.approx.ftz.f32 %0, %1;" : "=f"(y) : "f"(x));
    return y;
}
// ---- truncation-based bf16 split packing ----
__device__ __forceinline__ u32 pack_hi2(float a, float b) {
    return __byte_perm(__float_as_uint(a), __float_as_uint(b), 0x7632);
}
__device__ __forceinline__ float trunc_hi(float a) {
    return __uint_as_float(__float_as_uint(a) & 0xFFFF0000u);
}
__device__ __forceinline__ u32 pack_lo2(float a, float b) {
    float la = a - trunc_hi(a), lb = b - trunc_hi(b);
    u32 r;
    asm("cvt.rn.bf16x2.f32 %0, %1, %2;" : "=r"(r) : "f"(lb), "f"(la));
    return r;
}
// m16n8k16 row.col bf16 -> f32 accumulate (baseline PTX, works on sm_103 non-'a')
__device__ __forceinline__ void mma16816(float c[4], u32 a0, u32 a1, u32 a2, u32 a3,
                                         u32 b0, u32 b1) {
    asm volatile(
        "mma.sync.aligned.m16n8k16.row.col.f32.bf16.bf16.f32 "
        "{%0,%1,%2,%3}, {%4,%5,%6,%7}, {%8,%9}, {%0,%1,%2,%3};"
        : "+f"(c[0]), "+f"(c[1]), "+f"(c[2]), "+f"(c[3])
        : "r"(a0), "r"(a1), "r"(a2), "r"(a3), "r"(b0), "r"(b1));
}

// ---------------- Kernel 1: QKV projection + split/pack/permute ----------------
// block = 256 threads, 32 token rows. Q/K packed straight from registers via
// shuffle (quad-permuted, Q pre-scaled by SCALE2); V transposed via smem
// (pair-permuted).
#define WPITCH (HEAD + 1)
#define PROJ_ROWS 32
__global__ __launch_bounds__(256) void proj_kernel(const float* __restrict__ x,
                                                   const float* __restrict__ Wq,
                                                   const float* __restrict__ Wk,
                                                   const float* __restrict__ Wv) {
    __shared__ float sWq[EMBD * WPITCH];
    __shared__ float sWk[EMBD * WPITCH];
    __shared__ float sWv[EMBD * WPITCH];
    __shared__ float sx[PROJ_ROWS][EMBD];
    __shared__ float sv[PROJ_ROWS][33];

    int tid = threadIdx.x;
    for (int i = tid; i < EMBD * HEAD; i += 256) {
        int h = i / EMBD, d = i % EMBD;
        sWq[d * WPITCH + h] = Wq[i];
        sWk[d * WPITCH + h] = Wk[i];
        sWv[d * WPITCH + h] = Wv[i];
    }
    int row0 = blockIdx.x * PROJ_ROWS;
    for (int i = tid; i < PROJ_ROWS * EMBD; i += 256) {
        int r = i >> 5, c = i & 31;
        sx[r][c] = x[(row0 + r) * EMBD + c];
    }
    __syncthreads();

    int h = tid & 31;   // == lane
#pragma unroll
    for (int it = 0; it < 4; ++it) {
        int r = (tid >> 5) + 8 * it;
        float aq = 0.f, ak = 0.f, av = 0.f;
#pragma unroll
        for (int d = 0; d < EMBD; ++d) {
            float xv = sx[r][d];
            aq = fmaf(xv, sWq[d * WPITCH + h], aq);
            ak = fmaf(xv, sWk[d * WPITCH + h], ak);
            av = fmaf(xv, sWv[d * WPITCH + h], av);
        }
        float qs = aq * SCALE2;                      // fold softmax scale into Q
        float qs1 = __shfl_down_sync(0xffffffffu, qs, 1);
        float ak1 = __shfl_down_sync(0xffffffffu, ak, 1);
        if ((h & 1) == 0) {
            int h2 = h >> 1;
            int pos = 4 * (h2 & 3) + (h2 >> 2);      // quad permutation
            int gi = (row0 + r) * 16 + pos;
            g_qh[gi] = pack_hi2(qs, qs1);
            g_ql[gi] = pack_lo2(qs, qs1);
            g_kh[gi] = pack_hi2(ak, ak1);
            g_kl[gi] = pack_lo2(ak, ak1);
        }
        sv[r][h] = av;
    }
    __syncthreads();

    // V transposed + pair-permuted: block holds 16 key pairs (rows row0..row0+31)
    int bb = row0 / T_LEN;
    int trow = row0 - bb * T_LEN;
    for (int i = tid; i < HEAD * 16; i += 256) {
        int hh = i >> 4, kpl = i & 15;
        float v0 = sv[2 * kpl][hh], v1 = sv[2 * kpl + 1][hh];
        int kpg = (trow >> 1) + kpl;                 // global key-pair index
        int blk = kpg >> 6, wloc = kpg & 63;         // 64-word tile block
        int ks = wloc >> 3, rem = wloc & 7;
        int slot = 8 * ks + 2 * (rem & 3) + (rem >> 2);   // pair permutation
        int gi = (bb * HEAD + hh) * (T_LEN / 2) + (blk << 6) + slot;
        g_vth[gi] = pack_hi2(v0, v1);
        g_vtl[gi] = pack_lo2(v0, v1);
    }
}

// ---------------- Kernel 2: HMMA flash attention (split-K) ----------------
// grid = (T/QTILE, NSPLIT, BATCH), block = 128 (4 warps x 16 query rows each).
__global__ __launch_bounds__(NTHR) void flash_mma_kernel() {
    __shared__ __align__(16) u32 sKh[BC * KPITCH_W];
    __shared__ __align__(16) u32 sKl[BC * KPITCH_W];
    __shared__ __align__(16) u32 sVh[HEAD * VTPITCH_W];
    __shared__ __align__(16) u32 sVl[HEAD * VTPITCH_W];

    int qtile = blockIdx.x, split = blockIdx.y, b = blockIdx.z;
    int tid = threadIdx.x;
    int wid = tid >> 5, lane = tid & 31;
    int g = lane >> 2, t = lane & 3;

    int qbase = qtile * QTILE;
    int kv_begin = split * SPLIT_LEN;
    int kv_end = min(kv_begin + SPLIT_LEN, qbase + QTILE);   // block-uniform

    int q0 = qbase + wid * 16 + g;      // this thread's two query rows
    int q1 = q0 + 8;
    int pb0 = split * BT + b * T_LEN + q0;
    int pb1 = pb0 + 8;

    if (kv_begin >= kv_end) {           // split entirely above diagonal
        if (t == 0) {
            g_m[pb0] = -CUDART_INF_F; g_l[pb0] = 0.f;
            g_m[pb1] = -CUDART_INF_F; g_l[pb1] = 0.f;
        }
        return;
    }

    // ---- Q fragments: 4 LDG.128 of quad-permuted rows ----
    // quad(row, 4t..4t+3) = words (t, t+4, t+8, t+12) = (ks0.b0, ks0.b1, ks1.b0, ks1.b1)
    uint4 qh_r0, qh_r1, ql_r0, ql_r1;
    {
        int r0 = (b * T_LEN + q0) * 16 + 4 * t;
        int r1 = (b * T_LEN + q1) * 16 + 4 * t;
        qh_r0 = *(const uint4*)(g_qh + r0);
        qh_r1 = *(const uint4*)(g_qh + r1);
        ql_r0 = *(const uint4*)(g_ql + r0);
        ql_r1 = *(const uint4*)(g_ql + r1);
    }

    float m0 = -CUDART_INF_F, m1 = -CUDART_INF_F;
    float l0 = 0.f, l1 = 0.f;
    float O[4][4];
#pragma unroll
    for (int nb = 0; nb < 4; ++nb)
#pragma unroll
        for (int i = 0; i < 4; ++i) O[nb][i] = 0.f;

    for (int t0 = kv_begin; t0 < kv_end; t0 += BC) {
        // ---- stage: K is a linear copy (quad layout == gmem layout) ----
        __syncthreads();
        {
            const float4* skh = (const float4*)(g_kh + (b * T_LEN + t0) * 16);
            const float4* skl = (const float4*)(g_kl + (b * T_LEN + t0) * 16);
            float4* dkh = (float4*)sKh;
            float4* dkl = (float4*)sKl;
#pragma unroll
            for (int it = 0; it < 4; ++it) {          // 512 float4s each
                int f = it * NTHR + tid;
                dkh[f] = skh[f];
                dkl[f] = skl[f];
            }
            const float4* svh = (const float4*)(g_vth + b * HEAD * (T_LEN / 2));
            const float4* svl = (const float4*)(g_vtl + b * HEAD * (T_LEN / 2));
            int wbase = t0 >> 3;                      // float4 offset of this tile block
#pragma unroll
            for (int it = 0; it < 4; ++it) {          // 512 float4s each
                int f = it * NTHR + tid;
                int hh = f >> 4, w4 = f & 15;
                int src = hh * (T_LEN / 8) + wbase + w4;
                *(float4*)&sVh[hh * VTPITCH_W + 4 * w4] = svh[src];
                *(float4*)&sVl[hh * VTPITCH_W + 4 * w4] = svl[src];
            }
        }
        __syncthreads();

        // ---- S = Q K^T : 16 n-blocks, quad LDS.128 per matrix ----
        float sA[32], sB[32];
#pragma unroll
        for (int nb = 0; nb < 16; ++nb) {
            int key = nb * 8 + g;
            uint4 kqh = *(const uint4*)&sKh[key * KPITCH_W + 4 * t];
            uint4 kql = *(const uint4*)&sKl[key * KPITCH_W + 4 * t];
            float c[4] = {0.f, 0.f, 0.f, 0.f};
            mma16816(c, qh_r0.x, qh_r1.x, qh_r0.y, qh_r1.y, kqh.x, kqh.y);
            mma16816(c, qh_r0.z, qh_r1.z, qh_r0.w, qh_r1.w, kqh.z, kqh.w);
            mma16816(c, qh_r0.x, qh_r1.x, qh_r0.y, qh_r1.y, kql.x, kql.y);
            mma16816(c, qh_r0.z, qh_r1.z, qh_r0.w, qh_r1.w, kql.z, kql.w);
            mma16816(c, ql_r0.x, ql_r1.x, ql_r0.y, ql_r1.y, kqh.x, kqh.y);
            mma16816(c, ql_r0.z, ql_r1.z, ql_r0.w, ql_r1.w, kqh.z, kqh.w);
            sA[2 * nb]     = c[0]; sA[2 * nb + 1] = c[1];
            sB[2 * nb]     = c[2]; sB[2 * nb + 1] = c[3];
        }

        // ---- mask + row max (scores already scaled via Q) ----
        float mx0 = -CUDART_INF_F, mx1 = -CUDART_INF_F;
        if (t0 + BC > qbase) {
            // diagonal tile: causal mask needed
#pragma unroll
            for (int nb = 0; nb < 16; ++nb) {
#pragma unroll
                for (int i = 0; i < 2; ++i) {
                    int j = t0 + nb * 8 + 2 * t + i;
                    float a = sA[2 * nb + i];
                    float bs = sB[2 * nb + i];
                    // faithful: tril entries equal to exactly 0 are masked too
                    a  = (j <= q0 && a  != 0.0f) ? a  : -CUDART_INF_F;
                    bs = (j <= q1 && bs != 0.0f) ? bs : -CUDART_INF_F;
                    sA[2 * nb + i] = a;
                    sB[2 * nb + i] = bs;
                    mx0 = fmaxf(mx0, a);
                    mx1 = fmaxf(mx1, bs);
                }
            }
        } else {
            // interior tile: only the exact-zero faithfulness mask
#pragma unroll
            for (int k = 0; k < 32; ++k) {
                float a = sA[k], bs = sB[k];
                a  = (a  != 0.0f) ? a  : -CUDART_INF_F;
                bs = (bs != 0.0f) ? bs : -CUDART_INF_F;
                sA[k] = a; sB[k] = bs;
                mx0 = fmaxf(mx0, a);
                mx1 = fmaxf(mx1, bs);
            }
        }
        mx0 = fmaxf(mx0, __shfl_xor_sync(0xffffffffu, mx0, 1));
        mx0 = fmaxf(mx0, __shfl_xor_sync(0xffffffffu, mx0, 2));
        mx1 = fmaxf(mx1, __shfl_xor_sync(0xffffffffu, mx1, 1));
        mx1 = fmaxf(mx1, __shfl_xor_sync(0xffffffffu, mx1, 2));
        float m0n = fmaxf(m0, mx0);
        float m1n = fmaxf(m1, mx1);
        float c0 = exp2_approx(m0 - m0n);
        float c1 = exp2_approx(m1 - m1n);
        m0 = m0n; m1 = m1n;

        // ---- exp + row sums ----
        float ls0 = 0.f, ls1 = 0.f;
#pragma unroll
        for (int k = 0; k < 32; ++k) {
            float p0 = exp2_approx(sA[k] - m0n);
            float p1 = exp2_approx(sB[k] - m1n);
            sA[k] = p0; sB[k] = p1;
            ls0 += p0; ls1 += p1;
        }
        ls0 += __shfl_xor_sync(0xffffffffu, ls0, 1);
        ls0 += __shfl_xor_sync(0xffffffffu, ls0, 2);
        ls1 += __shfl_xor_sync(0xffffffffu, ls1, 1);
        ls1 += __shfl_xor_sync(0xffffffffu, ls1, 2);
        l0 = l0 * c0 + ls0;
        l1 = l1 * c1 + ls1;

#pragma unroll
        for (int nb = 0; nb < 4; ++nb) {
            O[nb][0] *= c0; O[nb][1] *= c0;
            O[nb][2] *= c1; O[nb][3] *= c1;
        }

        // ---- O += P V : pair LDS.64 b-fragments ----
#pragma unroll
        for (int ks = 0; ks < 8; ++ks) {
            float pa0 = sA[4 * ks],     pa1 = sA[4 * ks + 1];
            float pb0v = sB[4 * ks],    pb1v = sB[4 * ks + 1];
            float pa2 = sA[4 * ks + 2], pa3 = sA[4 * ks + 3];
            float pb2 = sB[4 * ks + 2], pb3 = sB[4 * ks + 3];
            u32 aph0 = pack_hi2(pa0, pa1);
            u32 aph1 = pack_hi2(pb0v, pb1v);
            u32 aph2 = pack_hi2(pa2, pa3);
            u32 aph3 = pack_hi2(pb2, pb3);
            u32 apl0 = pack_lo2(pa0, pa1);
            u32 apl1 = pack_lo2(pb0v, pb1v);
            u32 apl2 = pack_lo2(pa2, pa3);
            u32 apl3 = pack_lo2(pb2, pb3);
#pragma unroll
            for (int nb = 0; nb < 4; ++nb) {
                int hh = nb * 8 + g;
                uint2 vhp = *(const uint2*)&sVh[hh * VTPITCH_W + 8 * ks + 2 * t];
                uint2 vlp = *(const uint2*)&sVl[hh * VTPITCH_W + 8 * ks + 2 * t];
                mma16816(O[nb], aph0, aph1, aph2, aph3, vhp.x, vhp.y);
                mma16816(O[nb], aph0, aph1, aph2, aph3, vlp.x, vlp.y);
                mma16816(O[nb], apl0, apl1, apl2, apl3, vhp.x, vhp.y);
            }
        }
    }

    // ---- write partials ----
    if (t == 0) {
        g_m[pb0] = m0; g_l[pb0] = l0;
        g_m[pb1] = m1; g_l[pb1] = l1;
    }
    float* a0p = g_acc + pb0 * HEAD;
    float* a1p = g_acc + pb1 * HEAD;
#pragma unroll
    for (int nb = 0; nb < 4; ++nb) {
        int hc = nb * 8 + 2 * t;
        *(float2*)(a0p + hc) = make_float2(O[nb][0], O[nb][1]);
        *(float2*)(a1p + hc) = make_float2(O[nb][2], O[nb][3]);
    }
}

// ---------------- Kernel 3: split-K combine ----------------
__global__ void combine_kernel(float* __restrict__ out) {
    int bt = blockIdx.x * blockDim.x + threadIdx.x;
    if (bt >= BT) return;

    float ms[NSPLIT], ls[NSPLIT];
    float M = -CUDART_INF_F;
#pragma unroll
    for (int s = 0; s < NSPLIT; ++s) {
        ms[s] = g_m[s * BT + bt];
        ls[s] = g_l[s * BT + bt];
        M = fmaxf(M, ms[s]);
    }
    float w[NSPLIT];
    float L = 0.f;
#pragma unroll
    for (int s = 0; s < NSPLIT; ++s) {
        w[s] = (ms[s] == -CUDART_INF_F) ? 0.f : exp2_approx(ms[s] - M);
        L = fmaf(ls[s], w[s], L);
    }
    float inv = 1.0f / L;

    float4* og = reinterpret_cast<float4*>(out + bt * HEAD);
#pragma unroll
    for (int i = 0; i < 8; ++i) {
        float4 o = make_float4(0.f, 0.f, 0.f, 0.f);
#pragma unroll
        for (int s = 0; s < NSPLIT; ++s) {
            if (w[s] != 0.f) {
                const float4 a = reinterpret_cast<const float4*>(
                    g_acc + (s * BT + bt) * HEAD)[i];
                o.x = fmaf(a.x, w[s], o.x);
                o.y = fmaf(a.y, w[s], o.y);
                o.z = fmaf(a.z, w[s], o.z);
                o.w = fmaf(a.w, w[s], o.w);
            }
        }
        o.x *= inv; o.y *= inv; o.z *= inv; o.w *= inv;
        og[i] = o;
    }
}

extern "C" void kernel_launch(void* const* d_in, const int* in_sizes, int n_in,
                              void* d_out, int out_size) {
    const float* x  = (const float*)d_in[0];
    const float* Wq = (const float*)d_in[1];
    const float* Wk = (const float*)d_in[2];
    const float* Wv = (const float*)d_in[3];
    float* out = (float*)d_out;

    proj_kernel<<<BT / PROJ_ROWS, 256>>>(x, Wq, Wk, Wv);
    flash_mma_kernel<<<dim3(T_LEN / QTILE, NSPLIT, BATCH), NTHR>>>();
    combine_kernel<<<(BT + 127) / 128, 128>>>(out);
}

// round 17
// speedup vs baseline: 2.8337x; 1.1259x over previous
#include <cuda_runtime.h>
#include <cuda_bf16.h>
#include <math_constants.h>
#include <cstdint>

// Problem constants
#define BATCH 4
#define T_LEN 4096
#define EMBD 32
#define HEAD 32
#define BT (BATCH * T_LEN)

// Flash tiling (FA2-style, mma.sync m16n8k16 bf16)
#define NTHR 128               // 4 warps
#define QTILE 64               // queries per CTA (16 per warp)
#define BC 128                 // keys per tile
#define NSPLIT 8
#define SPLIT_LEN (T_LEN / NSPLIT)   // 512 = 4 key tiles

// scale * log2(e), folded into Q at pack time.
#define SCALE2 0.25505654309411853f

typedef unsigned int u32;

// smem word-offsets for the double-buffered tiles (dynamic smem)
// K: 128 rows x 16 words (quad layout). Vt: 32 rows x 72 words (pair layout).
#define KPITCH_W 16
#define VTPITCH_W 72
#define KH_OFF(buf) ((buf) * 2048)
#define KL_OFF(buf) (4096 + (buf) * 2048)
#define VH_OFF(buf) (8192 + (buf) * 2304)
#define VL_OFF(buf) (12800 + (buf) * 2304)
#define FLASH_SMEM_WORDS 17408
#define FLASH_SMEM_BYTES (FLASH_SMEM_WORDS * 4)   // 69632

// -------- device scratch (static globals; no allocation) --------
// quad-permuted packed rows: word (row, 4t+i) = bf16x2 of dims (2(t+4i), 2(t+4i)+1)
__device__ u32 g_qh[BT * 16];
__device__ u32 g_ql[BT * 16];
__device__ u32 g_kh[BT * 16];
__device__ u32 g_kl[BT * 16];
// pair-permuted transposed V: per 64-word tile block, slot 8ks+2t+i = keypair (8ks+t+4i)
__device__ u32 g_vth[BATCH * HEAD * (T_LEN / 2)];
__device__ u32 g_vtl[BATCH * HEAD * (T_LEN / 2)];
__device__ float g_m[NSPLIT * BT];
__device__ float g_l[NSPLIT * BT];
__device__ float g_acc[NSPLIT * BT * HEAD];

__device__ __forceinline__ float exp2_approx(float x) {
    float y;
    asm("ex2.approx.ftz.f32 %0, %1;" : "=f"(y) : "f"(x));
    return y;
}
// ---- truncation-based bf16 split packing ----
__device__ __forceinline__ u32 pack_hi2(float a, float b) {
    return __byte_perm(__float_as_uint(a), __float_as_uint(b), 0x7632);
}
__device__ __forceinline__ float trunc_hi(float a) {
    return __uint_as_float(__float_as_uint(a) & 0xFFFF0000u);
}
__device__ __forceinline__ u32 pack_lo2(float a, float b) {
    float la = a - trunc_hi(a), lb = b - trunc_hi(b);
    u32 r;
    asm("cvt.rn.bf16x2.f32 %0, %1, %2;" : "=r"(r) : "f"(lb), "f"(la));
    return r;
}
// m16n8k16 row.col bf16 -> f32 accumulate (baseline PTX, works on sm_103 non-'a')
__device__ __forceinline__ void mma16816(float c[4], u32 a0, u32 a1, u32 a2, u32 a3,
                                         u32 b0, u32 b1) {
    asm volatile(
        "mma.sync.aligned.m16n8k16.row.col.f32.bf16.bf16.f32 "
        "{%0,%1,%2,%3}, {%4,%5,%6,%7}, {%8,%9}, {%0,%1,%2,%3};"
        : "+f"(c[0]), "+f"(c[1]), "+f"(c[2]), "+f"(c[3])
        : "r"(a0), "r"(a1), "r"(a2), "r"(a3), "r"(b0), "r"(b1));
}
// ---- cp.async (LDGSTS; baseline sm_80 PTX) ----
__device__ __forceinline__ void cp_async16(u32 smem_addr, const void* gptr) {
    asm volatile("cp.async.cg.shared.global [%0], [%1], 16;"
                 :: "r"(smem_addr), "l"(gptr));
}
#define CP_COMMIT() asm volatile("cp.async.commit_group;" ::: "memory")

// ---------------- Kernel 1: QKV projection + split/pack/permute ----------------
// grid = 256, 2 row-groups of 32 per CTA (W smem fill amortized). Vector LDG.
#define WPITCH (HEAD + 1)
#define PROJ_ROWS 32
#define PROJ_GROUPS 2
__global__ __launch_bounds__(256) void proj_kernel(const float* __restrict__ x,
                                                   const float* __restrict__ Wq,
                                                   const float* __restrict__ Wk,
                                                   const float* __restrict__ Wv) {
    __shared__ float sWq[EMBD * WPITCH];
    __shared__ float sWk[EMBD * WPITCH];
    __shared__ float sWv[EMBD * WPITCH];
    __shared__ float sx[PROJ_ROWS][EMBD];
    __shared__ float sv[PROJ_ROWS][33];

    int tid = threadIdx.x;
    // W load: one float4 per thread per matrix; transposed STS (banks 4j+h, no conflicts)
    {
        float4 wq = ((const float4*)Wq)[tid];
        float4 wk = ((const float4*)Wk)[tid];
        float4 wv = ((const float4*)Wv)[tid];
        int h = tid >> 3, d0 = (tid & 7) * 4;
        sWq[(d0 + 0) * WPITCH + h] = wq.x; sWq[(d0 + 1) * WPITCH + h] = wq.y;
        sWq[(d0 + 2) * WPITCH + h] = wq.z; sWq[(d0 + 3) * WPITCH + h] = wq.w;
        sWk[(d0 + 0) * WPITCH + h] = wk.x; sWk[(d0 + 1) * WPITCH + h] = wk.y;
        sWk[(d0 + 2) * WPITCH + h] = wk.z; sWk[(d0 + 3) * WPITCH + h] = wk.w;
        sWv[(d0 + 0) * WPITCH + h] = wv.x; sWv[(d0 + 1) * WPITCH + h] = wv.y;
        sWv[(d0 + 2) * WPITCH + h] = wv.z; sWv[(d0 + 3) * WPITCH + h] = wv.w;
    }

    for (int grp = 0; grp < PROJ_GROUPS; ++grp) {
        int row0 = (blockIdx.x * PROJ_GROUPS + grp) * PROJ_ROWS;
        __syncthreads();   // W ready (grp 0) / sx, sv reuse safe (grp > 0)
        ((float4*)sx)[tid] = ((const float4*)(x + row0 * EMBD))[tid];
        __syncthreads();

        int h = tid & 31;   // == lane
#pragma unroll
        for (int it = 0; it < 4; ++it) {
            int r = (tid >> 5) + 8 * it;
            float aq = 0.f, ak = 0.f, av = 0.f;
#pragma unroll
            for (int d = 0; d < EMBD; ++d) {
                float xv = sx[r][d];
                aq = fmaf(xv, sWq[d * WPITCH + h], aq);
                ak = fmaf(xv, sWk[d * WPITCH + h], ak);
                av = fmaf(xv, sWv[d * WPITCH + h], av);
            }
            float qs = aq * SCALE2;                      // fold softmax scale into Q
            float qs1 = __shfl_down_sync(0xffffffffu, qs, 1);
            float ak1 = __shfl_down_sync(0xffffffffu, ak, 1);
            if ((h & 1) == 0) {
                int h2 = h >> 1;
                int pos = 4 * (h2 & 3) + (h2 >> 2);      // quad permutation
                int gi = (row0 + r) * 16 + pos;
                g_qh[gi] = pack_hi2(qs, qs1);
                g_ql[gi] = pack_lo2(qs, qs1);
                g_kh[gi] = pack_hi2(ak, ak1);
                g_kl[gi] = pack_lo2(ak, ak1);
            }
            sv[r][h] = av;
        }
        __syncthreads();

        // V transposed + pair-permuted
        int bb = row0 / T_LEN;
        int trow = row0 - bb * T_LEN;
        for (int i = tid; i < HEAD * 16; i += 256) {
            int hh = i >> 4, kpl = i & 15;
            float v0 = sv[2 * kpl][hh], v1 = sv[2 * kpl + 1][hh];
            int kpg = (trow >> 1) + kpl;
            int blk = kpg >> 6, wloc = kpg & 63;
            int ks = wloc >> 3, rem = wloc & 7;
            int slot = 8 * ks + 2 * (rem & 3) + (rem >> 2);
            int gi = (bb * HEAD + hh) * (T_LEN / 2) + (blk << 6) + slot;
            g_vth[gi] = pack_hi2(v0, v1);
            g_vtl[gi] = pack_lo2(v0, v1);
        }
    }
}

// ---------------- Kernel 2: HMMA flash attention (split-K, cp.async 2-stage) ----------------
__global__ __launch_bounds__(NTHR) void flash_mma_kernel() {
    extern __shared__ __align__(16) u32 dsm[];

    int qtile = blockIdx.x, split = blockIdx.y, b = blockIdx.z;
    int tid = threadIdx.x;
    int wid = tid >> 5, lane = tid & 31;
    int g = lane >> 2, t = lane & 3;

    int qbase = qtile * QTILE;
    int kv_begin = split * SPLIT_LEN;
    int kv_end = min(kv_begin + SPLIT_LEN, qbase + QTILE);   // block-uniform

    int q0 = qbase + wid * 16 + g;
    int q1 = q0 + 8;
    int pb0 = split * BT + b * T_LEN + q0;
    int pb1 = pb0 + 8;

    if (kv_begin >= kv_end) {
        if (t == 0) {
            g_m[pb0] = -CUDART_INF_F; g_l[pb0] = 0.f;
            g_m[pb1] = -CUDART_INF_F; g_l[pb1] = 0.f;
        }
        return;
    }

    u32 sbase = (u32)__cvta_generic_to_shared(dsm);
    const u32* gkh = g_kh + b * T_LEN * 16;
    const u32* gkl = g_kl + b * T_LEN * 16;
    const u32* gvh = g_vth + b * HEAD * (T_LEN / 2);
    const u32* gvl = g_vtl + b * HEAD * (T_LEN / 2);

    // ---- Q fragments: 4 LDG.128 of quad-permuted rows ----
    uint4 qh_r0, qh_r1, ql_r0, ql_r1;
    {
        int r0 = (b * T_LEN + q0) * 16 + 4 * t;
        int r1 = (b * T_LEN + q1) * 16 + 4 * t;
        qh_r0 = *(const uint4*)(g_qh + r0);
        qh_r1 = *(const uint4*)(g_qh + r1);
        ql_r0 = *(const uint4*)(g_ql + r0);
        ql_r1 = *(const uint4*)(g_ql + r1);
    }

    float m0 = -CUDART_INF_F, m1 = -CUDART_INF_F;
    float l0 = 0.f, l1 = 0.f;
    float O[4][4];
#pragma unroll
    for (int nb = 0; nb < 4; ++nb)
#pragma unroll
        for (int i = 0; i < 4; ++i) O[nb][i] = 0.f;

    // ---- async tile stage: K linear copy, Vt strided rows ----
    auto stage = [&](int t0, int buf) {
        const float4* skh = (const float4*)(gkh + t0 * 16);
        const float4* skl = (const float4*)(gkl + t0 * 16);
#pragma unroll
        for (int it = 0; it < 4; ++it) {
            int f = it * NTHR + tid;
            cp_async16(sbase + (KH_OFF(buf) + f * 4) * 4, skh + f);
            cp_async16(sbase + (KL_OFF(buf) + f * 4) * 4, skl + f);
        }
        int wbase = t0 >> 3;
        const float4* svh = (const float4*)gvh;
        const float4* svl = (const float4*)gvl;
#pragma unroll
        for (int it = 0; it < 4; ++it) {
            int f = it * NTHR + tid;
            int hh = f >> 4, w4 = f & 15;
            int src = hh * (T_LEN / 8) + wbase + w4;
            cp_async16(sbase + (VH_OFF(buf) + hh * VTPITCH_W + 4 * w4) * 4, svh + src);
            cp_async16(sbase + (VL_OFF(buf) + hh * VTPITCH_W + 4 * w4) * 4, svl + src);
        }
    };

    int ntiles = (kv_end - kv_begin + BC - 1) / BC;
    stage(kv_begin, 0);
    CP_COMMIT();

    for (int i = 0; i < ntiles; ++i) {
        int t0 = kv_begin + i * BC;
        bool has_next = (i + 1 < ntiles);
        if (has_next) {
            stage(t0 + BC, (i + 1) & 1);
            CP_COMMIT();
            asm volatile("cp.async.wait_group 1;" ::: "memory");
        } else {
            asm volatile("cp.async.wait_group 0;" ::: "memory");
        }
        __syncthreads();

        int cb = i & 1;
        const u32* sKh = dsm + KH_OFF(cb);
        const u32* sKl = dsm + KL_OFF(cb);
        const u32* sVh = dsm + VH_OFF(cb);
        const u32* sVl = dsm + VL_OFF(cb);

        // ---- S = Q K^T : 16 n-blocks, quad LDS.128 per matrix ----
        float sA[32], sB[32];
#pragma unroll
        for (int nb = 0; nb < 16; ++nb) {
            int key = nb * 8 + g;
            uint4 kqh = *(const uint4*)&sKh[key * KPITCH_W + 4 * t];
            uint4 kql = *(const uint4*)&sKl[key * KPITCH_W + 4 * t];
            float c[4] = {0.f, 0.f, 0.f, 0.f};
            mma16816(c, qh_r0.x, qh_r1.x, qh_r0.y, qh_r1.y, kqh.x, kqh.y);
            mma16816(c, qh_r0.z, qh_r1.z, qh_r0.w, qh_r1.w, kqh.z, kqh.w);
            mma16816(c, qh_r0.x, qh_r1.x, qh_r0.y, qh_r1.y, kql.x, kql.y);
            mma16816(c, qh_r0.z, qh_r1.z, qh_r0.w, qh_r1.w, kql.z, kql.w);
            mma16816(c, ql_r0.x, ql_r1.x, ql_r0.y, ql_r1.y, kqh.x, kqh.y);
            mma16816(c, ql_r0.z, ql_r1.z, ql_r0.w, ql_r1.w, kqh.z, kqh.w);
            sA[2 * nb]     = c[0]; sA[2 * nb + 1] = c[1];
            sB[2 * nb]     = c[2]; sB[2 * nb + 1] = c[3];
        }

        // ---- mask + row max (scores pre-scaled via Q) ----
        float mx0 = -CUDART_INF_F, mx1 = -CUDART_INF_F;
        if (t0 + BC > qbase) {
#pragma unroll
            for (int nb = 0; nb < 16; ++nb) {
#pragma unroll
                for (int i2 = 0; i2 < 2; ++i2) {
                    int j = t0 + nb * 8 + 2 * t + i2;
                    float a = sA[2 * nb + i2];
                    float bs = sB[2 * nb + i2];
                    // faithful: tril entries equal to exactly 0 are masked too
                    a  = (j <= q0 && a  != 0.0f) ? a  : -CUDART_INF_F;
                    bs = (j <= q1 && bs != 0.0f) ? bs : -CUDART_INF_F;
                    sA[2 * nb + i2] = a;
                    sB[2 * nb + i2] = bs;
                    mx0 = fmaxf(mx0, a);
                    mx1 = fmaxf(mx1, bs);
                }
            }
        } else {
#pragma unroll
            for (int k = 0; k < 32; ++k) {
                float a = sA[k], bs = sB[k];
                a  = (a  != 0.0f) ? a  : -CUDART_INF_F;
                bs = (bs != 0.0f) ? bs : -CUDART_INF_F;
                sA[k] = a; sB[k] = bs;
                mx0 = fmaxf(mx0, a);
                mx1 = fmaxf(mx1, bs);
            }
        }
        mx0 = fmaxf(mx0, __shfl_xor_sync(0xffffffffu, mx0, 1));
        mx0 = fmaxf(mx0, __shfl_xor_sync(0xffffffffu, mx0, 2));
        mx1 = fmaxf(mx1, __shfl_xor_sync(0xffffffffu, mx1, 1));
        mx1 = fmaxf(mx1, __shfl_xor_sync(0xffffffffu, mx1, 2));
        float m0n = fmaxf(m0, mx0);
        float m1n = fmaxf(m1, mx1);
        float c0 = exp2_approx(m0 - m0n);
        float c1 = exp2_approx(m1 - m1n);
        m0 = m0n; m1 = m1n;

        // ---- exp + row sums ----
        float ls0 = 0.f, ls1 = 0.f;
#pragma unroll
        for (int k = 0; k < 32; ++k) {
            float p0 = exp2_approx(sA[k] - m0n);
            float p1 = exp2_approx(sB[k] - m1n);
            sA[k] = p0; sB[k] = p1;
            ls0 += p0; ls1 += p1;
        }
        ls0 += __shfl_xor_sync(0xffffffffu, ls0, 1);
        ls0 += __shfl_xor_sync(0xffffffffu, ls0, 2);
        ls1 += __shfl_xor_sync(0xffffffffu, ls1, 1);
        ls1 += __shfl_xor_sync(0xffffffffu, ls1, 2);
        l0 = l0 * c0 + ls0;
        l1 = l1 * c1 + ls1;

#pragma unroll
        for (int nb = 0; nb < 4; ++nb) {
            O[nb][0] *= c0; O[nb][1] *= c0;
            O[nb][2] *= c1; O[nb][3] *= c1;
        }

        // ---- O += P V : pair LDS.64 b-fragments ----
#pragma unroll
        for (int ks = 0; ks < 8; ++ks) {
            float pa0 = sA[4 * ks],     pa1 = sA[4 * ks + 1];
            float pb0v = sB[4 * ks],    pb1v = sB[4 * ks + 1];
            float pa2 = sA[4 * ks + 2], pa3 = sA[4 * ks + 3];
            float pb2 = sB[4 * ks + 2], pb3 = sB[4 * ks + 3];
            u32 aph0 = pack_hi2(pa0, pa1);
            u32 aph1 = pack_hi2(pb0v, pb1v);
            u32 aph2 = pack_hi2(pa2, pa3);
            u32 aph3 = pack_hi2(pb2, pb3);
            u32 apl0 = pack_lo2(pa0, pa1);
            u32 apl1 = pack_lo2(pb0v, pb1v);
            u32 apl2 = pack_lo2(pa2, pa3);
            u32 apl3 = pack_lo2(pb2, pb3);
#pragma unroll
            for (int nb = 0; nb < 4; ++nb) {
                int hh = nb * 8 + g;
                uint2 vhp = *(const uint2*)&sVh[hh * VTPITCH_W + 8 * ks + 2 * t];
                uint2 vlp = *(const uint2*)&sVl[hh * VTPITCH_W + 8 * ks + 2 * t];
                mma16816(O[nb], aph0, aph1, aph2, aph3, vhp.x, vhp.y);
                mma16816(O[nb], aph0, aph1, aph2, aph3, vlp.x, vlp.y);
                mma16816(O[nb], apl0, apl1, apl2, apl3, vhp.x, vhp.y);
            }
        }
        __syncthreads();   // all reads of buf cb done before it's re-staged
    }

    // ---- write partials ----
    if (t == 0) {
        g_m[pb0] = m0; g_l[pb0] = l0;
        g_m[pb1] = m1; g_l[pb1] = l1;
    }
    float* a0p = g_acc + pb0 * HEAD;
    float* a1p = g_acc + pb1 * HEAD;
#pragma unroll
    for (int nb = 0; nb < 4; ++nb) {
        int hc = nb * 8 + 2 * t;
        *(float2*)(a0p + hc) = make_float2(O[nb][0], O[nb][1]);
        *(float2*)(a1p + hc) = make_float2(O[nb][2], O[nb][3]);
    }
}

// ---------------- Kernel 3: split-K combine ----------------
__global__ void combine_kernel(float* __restrict__ out) {
    int bt = blockIdx.x * blockDim.x + threadIdx.x;
    if (bt >= BT) return;

    float ms[NSPLIT], ls[NSPLIT];
    float M = -CUDART_INF_F;
#pragma unroll
    for (int s = 0; s < NSPLIT; ++s) {
        ms[s] = g_m[s * BT + bt];
        ls[s] = g_l[s * BT + bt];
        M = fmaxf(M, ms[s]);
    }
    float w[NSPLIT];
    float L = 0.f;
#pragma unroll
    for (int s = 0; s < NSPLIT; ++s) {
        w[s] = (ms[s] == -CUDART_INF_F) ? 0.f : exp2_approx(ms[s] - M);
        L = fmaf(ls[s], w[s], L);
    }
    float inv = 1.0f / L;

    float4* og = reinterpret_cast<float4*>(out + bt * HEAD);
#pragma unroll
    for (int i = 0; i < 8; ++i) {
        float4 o = make_float4(0.f, 0.f, 0.f, 0.f);
#pragma unroll
        for (int s = 0; s < NSPLIT; ++s) {
            if (w[s] != 0.f) {
                const float4 a = reinterpret_cast<const float4*>(
                    g_acc + (s * BT + bt) * HEAD)[i];
                o.x = fmaf(a.x, w[s], o.x);
                o.y = fmaf(a.y, w[s], o.y);
                o.z = fmaf(a.z, w[s], o.z);
                o.w = fmaf(a.w, w[s], o.w);
            }
        }
        o.x *= inv; o.y *= inv; o.z *= inv; o.w *= inv;
        og[i] = o;
    }
}

extern "C" void kernel_launch(void* const* d_in, const int* in_sizes, int n_in,
                              void* d_out, int out_size) {
    const float* x  = (const float*)d_in[0];
    const float* Wq = (const float*)d_in[1];
    const float* Wk = (const float*)d_in[2];
    const float* Wv = (const float*)d_in[3];
    float* out = (float*)d_out;

    cudaFuncSetAttribute(flash_mma_kernel,
                         cudaFuncAttributeMaxDynamicSharedMemorySize,
                         FLASH_SMEM_BYTES);

    proj_kernel<<<BT / (PROJ_ROWS * PROJ_GROUPS), 256>>>(x, Wq, Wk, Wv);
    flash_mma_kernel<<<dim3(T_LEN / QTILE, NSPLIT, BATCH), NTHR,
                       FLASH_SMEM_BYTES>>>();
    combine_kernel<<<(BT + 127) / 128, 128>>>(out);
}